// round 9
// baseline (speedup 1.0000x reference)
#include <cuda_runtime.h>

#define BATCH   32
#define D_IN    1024
#define D_OUT   1024
#define E_DIM   3076                 // D_OUT + 2*D_IN + 4
#define NROWBLK 147
#define GWN     (NROWBLK * 8)        // 1176 row-warps
#define KQ_TOTAL 2052u               // rows with e >= 1024

// Scratch + sync (allocation-free rule: __device__ globals)
__device__ float    g_out [BATCH * E_DIM];   // only e >= D_OUT used
__device__ float    g_kphi[BATCH * D_IN];
__device__ float    g_qphi[BATCH * D_IN];
__device__ float    g_sig [BATCH * 4];
__device__ unsigned g_cnt [BATCH];
__device__ unsigned g_flag[BATCH];

__global__ void srwm_init()
{
    for (int i = 0; i < BATCH; i++) { g_cnt[i] = 0; g_flag[i] = 0; }
}

// ---------------------------------------------------------------------------
// Row helpers: w row lives in buf[32] (per-lane quarter of the 1024 floats).
// ---------------------------------------------------------------------------
__device__ __forceinline__ void mv_row(const float* __restrict__ w,
                                       const float* __restrict__ x,
                                       float* __restrict__ y, int write_y,
                                       int b, int e, int lane, float (&buf)[32])
{
    const float4* wrow = (const float4*)(w + ((size_t)b * E_DIM + e) * D_IN);
    const float4* x4   = (const float4*)(x + (size_t)b * D_IN);
    float acc = 0.f;
#pragma unroll
    for (int j = 0; j < 8; j++) {
        float4 wv = wrow[lane + j * 32];
        float4 xv = __ldg(x4 + lane + j * 32);
        buf[4*j] = wv.x; buf[4*j+1] = wv.y; buf[4*j+2] = wv.z; buf[4*j+3] = wv.w;
        acc += wv.x * xv.x + wv.y * xv.y + wv.z * xv.z + wv.w * xv.w;
    }
#pragma unroll
    for (int o = 16; o; o >>= 1) acc += __shfl_xor_sync(0xffffffffu, acc, o);
    if (lane == 0) {
        if (e >= D_OUT) g_out[(size_t)b * E_DIM + e] = acc;
        else if (write_y) y[(size_t)b * D_OUT + e] = acc;
    }
}

__device__ __forceinline__ void up_row(float* __restrict__ wout,
                                       int b, int e, int lane,
                                       const float (&buf)[32])
{
    const float4* kp = (const float4*)(g_kphi + (size_t)b * D_IN);
    const float4* qp = (const float4*)(g_qphi + (size_t)b * D_IN);
    float ab = 0.f, av = 0.f;
#pragma unroll
    for (int j = 0; j < 8; j++) {
        float4 kv = __ldg(kp + lane + j * 32);
        float4 qv = __ldg(qp + lane + j * 32);
        ab += buf[4*j]*kv.x + buf[4*j+1]*kv.y + buf[4*j+2]*kv.z + buf[4*j+3]*kv.w;
        av += buf[4*j]*qv.x + buf[4*j+1]*qv.y + buf[4*j+2]*qv.z + buf[4*j+3]*qv.w;
    }
#pragma unroll
    for (int o = 16; o; o >>= 1) {
        ab += __shfl_xor_sync(0xffffffffu, ab, o);
        av += __shfl_xor_sync(0xffffffffu, av, o);
    }
    const int seg = (e < D_OUT) ? 0 : (e < D_OUT + D_IN) ? 1 :
                    (e < D_OUT + 2 * D_IN) ? 2 : 3;
    const float coeff = __ldg(&g_sig[b * 4 + seg]) * (av - ab);
    float4* orow = (float4*)(wout + ((size_t)b * E_DIM + e) * D_IN);
#pragma unroll
    for (int j = 0; j < 8; j++) {
        float4 kv = __ldg(kp + lane + j * 32);
        float4 o4 = { buf[4*j]   + coeff * kv.x, buf[4*j+1] + coeff * kv.y,
                      buf[4*j+2] + coeff * kv.z, buf[4*j+3] + coeff * kv.w };
        __stcs(orow + lane + j * 32, o4);
    }
}

// ---------------------------------------------------------------------------
// Softmax warp (block 0): 1024-value softmax entirely in one warp.
// ---------------------------------------------------------------------------
__device__ __forceinline__ void softmax1024(const float* __restrict__ src,
                                            float* __restrict__ dst, int lane)
{
    float4 v[8];
    float m = -1e30f;
#pragma unroll
    for (int j = 0; j < 8; j++) {
        v[j] = __ldcg(((const float4*)src) + lane + j * 32);
        m = fmaxf(m, fmaxf(fmaxf(v[j].x, v[j].y), fmaxf(v[j].z, v[j].w)));
    }
#pragma unroll
    for (int o = 16; o; o >>= 1) m = fmaxf(m, __shfl_xor_sync(0xffffffffu, m, o));
    float s = 0.f;
#pragma unroll
    for (int j = 0; j < 8; j++) {
        v[j].x = __expf(v[j].x - m); v[j].y = __expf(v[j].y - m);
        v[j].z = __expf(v[j].z - m); v[j].w = __expf(v[j].w - m);
        s += v[j].x + v[j].y + v[j].z + v[j].w;
    }
#pragma unroll
    for (int o = 16; o; o >>= 1) s += __shfl_xor_sync(0xffffffffu, s, o);
    const float inv = 1.0f / s;
#pragma unroll
    for (int j = 0; j < 8; j++) {
        float4 o4 = { v[j].x * inv, v[j].y * inv, v[j].z * inv, v[j].w * inv };
        ((float4*)dst)[lane + j * 32] = o4;
    }
}

// ---------------------------------------------------------------------------
// Fused persistent kernel. Block 0 = softmax/sigmoid server; blocks 1..147
// are row blocks (8 warps, 3 rows each, double-buffered across batches).
// ---------------------------------------------------------------------------
__global__ void __launch_bounds__(256, 1)
srwm_fused(const float* __restrict__ w, const float* __restrict__ x,
           float* __restrict__ y, float* __restrict__ wout, int write_y)
{
    const int tid  = threadIdx.x;
    const int wid  = tid >> 5;
    const int lane = tid & 31;
    const int bid  = blockIdx.x;

    if (bid == 0) {
        // ---------------- softmax / sigmoid server ----------------
        if (wid > 2) return;
        for (int b = 0; b < BATCH; b++) {
            while (*(volatile unsigned*)&g_cnt[b] < KQ_TOTAL) __nanosleep(64);
            __threadfence();
            if (wid == 0) {
                softmax1024(g_out + (size_t)b * E_DIM + D_OUT,
                            g_kphi + (size_t)b * D_IN, lane);
            } else if (wid == 1) {
                softmax1024(g_out + (size_t)b * E_DIM + D_OUT + D_IN,
                            g_qphi + (size_t)b * D_IN, lane);
            } else {
                if (lane < 4) {
                    float t = __ldcg(&g_out[(size_t)b * E_DIM + D_OUT + 2 * D_IN + lane]);
                    g_sig[b * 4 + lane] = 1.0f / (1.0f + __expf(-t));
                }
            }
            __threadfence();
            if (lane == 0) atomicAdd(&g_flag[b], 1u);
        }
        return;
    }

    // ---------------- row blocks ----------------
    const int gw = (bid - 1) * 8 + wid;          // 0..1175
    const int e0 = gw;                            // kq iff gw >= D_OUT
    const int e1 = gw + GWN;                      // always kq (1176..2351)
    const int e2 = gw + 2 * GWN;                  // valid iff < E_DIM
    const bool v2  = (e2 < E_DIM);
    const bool kq0 = (e0 >= D_OUT);
    const unsigned nkq = (kq0 ? 1u : 0u) + 1u + (v2 ? 1u : 0u);

    float A0[32], A1[32], A2[32];
    float B0[32], B1[32], B2[32];

    auto mv_kq = [&](float (&r0)[32], float (&r1)[32], float (&r2)[32], int b) {
        if (kq0) mv_row(w, x, y, write_y, b, e0, lane, r0);
        mv_row(w, x, y, write_y, b, e1, lane, r1);
        if (v2)  mv_row(w, x, y, write_y, b, e2, lane, r2);
        __threadfence();
        if (lane == 0) atomicAdd(&g_cnt[b], nkq);
    };
    auto mv_y = [&](float (&r0)[32], int b) {
        if (!kq0) mv_row(w, x, y, write_y, b, e0, lane, r0);
    };
    auto waitflag = [&](int b) {
        while (*(volatile unsigned*)&g_flag[b] < 3u) __nanosleep(64);
        __threadfence();
    };
    auto upd = [&](float (&r0)[32], float (&r1)[32], float (&r2)[32], int b) {
        up_row(wout, b, e0, lane, r0);
        up_row(wout, b, e1, lane, r1);
        if (v2) up_row(wout, b, e2, lane, r2);
    };

    // prologue: batch 0 fully loaded + counted
    mv_kq(A0, A1, A2, 0);
    mv_y(A0, 0);

#pragma unroll 1
    for (int bb = 0; bb < BATCH; bb += 2) {
        // load kq rows of bb+1 (posts count -> softmax(bb+1) runs concurrently)
        mv_kq(B0, B1, B2, bb + 1);
        // update bb from registers
        waitflag(bb);
        upd(A0, A1, A2, bb);
        mv_y(B0, bb + 1);

        if (bb + 2 < BATCH) mv_kq(A0, A1, A2, bb + 2);
        waitflag(bb + 1);
        upd(B0, B1, B2, bb + 1);
        if (bb + 2 < BATCH) mv_y(A0, bb + 2);
    }
}

// ---------------------------------------------------------------------------
// kernel_launch: init + one fused kernel (2 graph nodes).
// ---------------------------------------------------------------------------
extern "C" void kernel_launch(void* const* d_in, const int* in_sizes, int n_in,
                              void* d_out, int out_size)
{
    const float* x = (const float*)d_in[0];
    const float* w = (const float*)d_in[1];
    if (n_in >= 2 && in_sizes[0] != BATCH * D_IN) {
        x = (const float*)d_in[1];
        w = (const float*)d_in[0];
    }

    const size_t wout_elems = (size_t)BATCH * E_DIM * D_IN;
    float* out = (float*)d_out;

    float* y_ptr    = out;
    float* wout_ptr = out + ((size_t)out_size - wout_elems);
    const int write_y = ((size_t)out_size > wout_elems) ? 1 : 0;

    srwm_init<<<1, 1>>>();
    srwm_fused<<<1 + NROWBLK, 256>>>(w, x, y_ptr, wout_ptr, write_y);
}